// round 8
// baseline (speedup 1.0000x reference)
#include <cuda_runtime.h>
#include <cuda_fp16.h>
#include <cstdint>
#include <cstddef>

#define H 512
#define W 512
#define C 128
#define TI 16
#define TJ 16
// weights smem: [16 i][16 j][64 t], i-stride 1024 -> 1028 words (== 4 mod 16)
// -> row-pair lanes (stride 2*1028 words == 8 mod 32 banks) land at bank
//    groups {0,8,16,24}: conflict-free 16B broadcast loads.
#define WISTRIDE 1028
#define W3_FLOATS (16 * WISTRIDE)          // 16448
// x halo (fp16): [8 chg][23 rows][28 cols][4 ch] in half2 units.
// chunk = 23*28*2 = 1288 -> pad 1290 (== 10 mod 32: 8 chgs hit 16 distinct banks)
// row stride = 28*2 = 56 uint32 -> row-pair stride 112 == 16 mod 32.
#define XROWU 56                            // uint32 per halo row
#define XCHUNK2 1290                        // uint32 (half2) per chg
#define XS_FLOATS (8 * XCHUNK2)             // 10320 floats-equivalent
#define SMEM_FLOATS (W3_FLOATS + XS_FLOATS + 529 + 256)
#define SMEM_BYTES (SMEM_FLOATS * 4)        // 110,212 B -> 2 CTAs/SM

typedef unsigned long long ull;

__device__ __forceinline__ ull pack2(float a, float b) {
    ull r; asm("mov.b64 %0, {%1, %2};" : "=l"(r) : "f"(a), "f"(b)); return r;
}
__device__ __forceinline__ void fma2(ull& d, ull a, ull b) {
    asm("fma.rn.f32x2 %0, %1, %2, %0;" : "+l"(d) : "l"(a), "l"(b));
}
__device__ __forceinline__ float2 unpack2(ull v) {
    float2 f; asm("mov.b64 {%0, %1}, %2;" : "=f"(f.x), "=f"(f.y) : "l"(v)); return f;
}
__device__ __forceinline__ void cp_async16(float* smem_dst, const float* gsrc) {
    uint32_t s = (uint32_t)__cvta_generic_to_shared(smem_dst);
    asm volatile("cp.async.cg.shared.global [%0], [%1], 16;\n"
                 :: "r"(s), "l"(gsrc));
}
__device__ __forceinline__ void cp_async4(float* smem_dst, const float* gsrc, bool pred) {
    uint32_t s = (uint32_t)__cvta_generic_to_shared(smem_dst);
    int sz = pred ? 4 : 0;
    asm volatile("cp.async.ca.shared.global [%0], [%1], 4, %2;\n"
                 :: "r"(s), "l"(gsrc), "r"(sz));
}
__device__ __forceinline__ void cp_commit() {
    asm volatile("cp.async.commit_group;\n" ::: "memory");
}
template <int N> __device__ __forceinline__ void cp_wait() {
    asm volatile("cp.async.wait_group %0;\n" :: "n"(N) : "memory");
}

// ---- stage one 32-channel x pass: LDG fp32 -> cvt fp16 -> STS ----
__device__ __forceinline__ void stage_x(uint32_t* xs2, const float* __restrict__ gx,
                                        int bi, int bj, int pass, int tid) {
    const int cbase = pass * 32;
    #pragma unroll 2
    for (int u = tid; u < 529 * 8; u += 128) {
        int q = u & 7, pix = u >> 3;
        int hr = pix / 23, hc = pix - hr * 23;
        int gr = bi + hr - 3, gcl = bj + hc - 3;
        float4 v = make_float4(0.f, 0.f, 0.f, 0.f);
        if ((unsigned)gr < H && (unsigned)gcl < W)
            v = *(const float4*)(gx + (((size_t)gr * W + gcl) * C + cbase + q * 4));
        __half2 h0 = __float22half2_rn(make_float2(v.x, v.y));
        __half2 h1 = __float22half2_rn(make_float2(v.z, v.w));
        uint2 st;
        st.x = *(uint32_t*)&h0;
        st.y = *(uint32_t*)&h1;
        *(uint2*)(xs2 + q * XCHUNK2 + (hr * 28 + hc) * 2) = st;
    }
}

// ---- compute one pass: 2 rows x 8 cols x 4 ch per thread ----
__device__ __forceinline__ void compute_pass(const uint32_t* __restrict__ xs2,
                                             const float* __restrict__ w3,
                                             const float* __restrict__ inv,
                                             float* __restrict__ gout,
                                             int bi, int bj, int cbase,
                                             int r0, int j0, int chg) {
    ull acc[2][8][2];
    #pragma unroll
    for (int d = 0; d < 2; ++d)
        #pragma unroll
        for (int j = 0; j < 8; ++j) { acc[d][j][0] = 0ull; acc[d][j][1] = 0ull; }

    const uint32_t* xb = xs2 + chg * XCHUNK2 + j0 * 2;   // col base = j0
    const float*    wb = w3 + r0 * WISTRIDE + j0 * 64;

    #pragma unroll
    for (int xr = 0; xr < 9; ++xr) {                 // halo row r0+xr
        // load + convert 15-position halo row (4 fp16 ch each)
        ull xf[15][2];
        const uint2* xp = (const uint2*)(xb + (r0 + xr) * XROWU);
        #pragma unroll
        for (int t = 0; t < 15; ++t) {
            uint2 h = xp[t];
            float2 f01 = __half22float2(*(__half2*)&h.x);
            float2 f23 = __half22float2(*(__half2*)&h.y);
            xf[t][0] = pack2(f01.x, f01.y);
            xf[t][1] = pack2(f23.x, f23.y);
        }
        #pragma unroll
        for (int di = 0; di < 2; ++di) {
            const int p = xr - di;
            if (p < 0 || p > 7) continue;            // compile-time
            const float* wr = wb + di * WISTRIDE + p * 8;
            #pragma unroll
            for (int j = 0; j < 8; ++j) {
                #pragma unroll
                for (int qg = 0; qg < 2; ++qg) {
                    float4 w4 = *(const float4*)(wr + j * 64 + qg * 4);
                    const int t0 = j + qg * 4;
                    ull w0 = pack2(w4.x, w4.x);
                    ull w1 = pack2(w4.y, w4.y);
                    ull w2 = pack2(w4.z, w4.z);
                    ull w3p = pack2(w4.w, w4.w);
                    fma2(acc[di][j][0], xf[t0 + 0][0], w0);
                    fma2(acc[di][j][1], xf[t0 + 0][1], w0);
                    fma2(acc[di][j][0], xf[t0 + 1][0], w1);
                    fma2(acc[di][j][1], xf[t0 + 1][1], w1);
                    fma2(acc[di][j][0], xf[t0 + 2][0], w2);
                    fma2(acc[di][j][1], xf[t0 + 2][1], w2);
                    fma2(acc[di][j][0], xf[t0 + 3][0], w3p);
                    fma2(acc[di][j][1], xf[t0 + 3][1], w3p);
                }
            }
        }
    }

    // ---- normalize + store (8 chg lanes -> 128B contiguous per (row,j)) ----
    #pragma unroll
    for (int di = 0; di < 2; ++di) {
        #pragma unroll
        for (int j = 0; j < 8; ++j) {
            float s = inv[(r0 + di) * 16 + j0 + j];
            float2 a0 = unpack2(acc[di][j][0]);
            float2 a1 = unpack2(acc[di][j][1]);
            float4 v = make_float4(a0.x * s, a0.y * s, a1.x * s, a1.y * s);
            *(float4*)(gout + (((size_t)(bi + r0 + di) * W + (bj + j0 + j)) * C
                               + cbase + chg * 4)) = v;
        }
    }
}

__global__ __launch_bounds__(128, 2) void cell_att_kernel(
    const float* __restrict__ gx,   // [H][W][C]
    const float* __restrict__ gw,   // [H][W][64]
    const float* __restrict__ gc,   // [H][W]
    float* __restrict__ gout)       // [H][W][C]
{
    extern __shared__ float smem[];
    float*    w3  = smem;                        // fp32 weights
    uint32_t* xs2 = (uint32_t*)(w3 + W3_FLOATS); // fp16 x halo (half2 units)
    float*    ch  = (float*)(xs2 + XS_FLOATS);   // 23x23 cnts halo (fp32)
    float*    inv = ch + 529;                    // 256 per-pixel normalizers

    const int tid = threadIdx.x;
    const int chg = tid & 7;            // channel quad (4 ch)
    const int rp  = (tid >> 3) & 7;     // row pair -> rows 2rp, 2rp+1
    const int jg  = tid >> 6;           // 0 or 1
    const int r0 = rp * 2, j0 = jg * 8;
    const int bi = blockIdx.y * TI, bj = blockIdx.x * TJ;

    // ---- stage weights (cp.async, natural layout) + cnts halo ----
    #pragma unroll 4
    for (int u = tid; u < 256 * 16; u += 128) {
        int quad = u & 15, px = u >> 4;
        int il = px >> 4, jl = px & 15;
        const float* src = gw + ((size_t)(bi + il) * W + (bj + jl)) * 64 + quad * 4;
        cp_async16(w3 + il * WISTRIDE + jl * 64 + quad * 4, src);
    }
    for (int u = tid; u < 529; u += 128) {
        int hr = u / 23, hc = u - hr * 23;
        int gr = bi + hr - 3, gcl = bj + hc - 3;
        bool ok = ((unsigned)gr < H) && ((unsigned)gcl < W);
        const float* src = ok ? gc + (size_t)gr * W + gcl : gc;
        cp_async4(ch + u, src, ok);
    }
    cp_commit();

    // ---- stage x pass 0 (overlaps the cp.async above) ----
    stage_x(xs2, gx, bi, bj, 0, tid);

    cp_wait<0>();
    __syncthreads();                    // w3, ch, xs2(pass0) all visible

    // ---- normalizer: inv = 1/(att(cnts)+1e-6), 2 pixels per thread ----
    #pragma unroll
    for (int rep = 0; rep < 2; ++rep) {
        int px = tid + rep * 128;
        int il = px >> 4, jl = px & 15;
        const float* wpx = w3 + il * WISTRIDE + jl * 64;
        float s = 0.f;
        #pragma unroll
        for (int p = 0; p < 8; ++p)
            #pragma unroll
            for (int q = 0; q < 8; ++q)
                s += ch[(il + p) * 23 + (jl + q)] * wpx[p * 8 + q];
        inv[px] = 1.0f / (s + 1e-6f);
    }
    __syncthreads();                    // inv visible

    compute_pass(xs2, w3, inv, gout, bi, bj, 0, r0, j0, chg);

    #pragma unroll 1
    for (int pass = 1; pass < 4; ++pass) {
        __syncthreads();                // everyone done reading xs2
        stage_x(xs2, gx, bi, bj, pass, tid);
        __syncthreads();                // new xs2 visible
        compute_pass(xs2, w3, inv, gout, bi, bj, pass * 32, r0, j0, chg);
    }
}

extern "C" void kernel_launch(void* const* d_in, const int* in_sizes, int n_in,
                              void* d_out, int out_size) {
    const float* x0 = (const float*)d_in[0];
    const float* w  = (const float*)d_in[1];
    const float* c  = (const float*)d_in[2];
    float* out      = (float*)d_out;
    cudaFuncSetAttribute(cell_att_kernel,
                         cudaFuncAttributeMaxDynamicSharedMemorySize, SMEM_BYTES);
    dim3 grid(W / TJ, H / TI);
    cell_att_kernel<<<grid, 128, SMEM_BYTES>>>(x0, w, c, out);
}

// round 10
// speedup vs baseline: 1.4721x; 1.4721x over previous
#include <cuda_runtime.h>
#include <cuda_fp16.h>
#include <cstdint>
#include <cstddef>

#define H 512
#define W 512
#define C 128
#define TI 16
#define TJ 16
// weights smem: [16 i][16 j][64 t] fp32, i-stride 1024 -> 1028 (== 4 mod 32):
// the 4 row-lanes of a warp land on bank groups {0,4,8,12}+c -> 16 distinct
// banks for 4x16B: one wavefront.
#define WISTRIDE 1028
#define W3_FLOATS (16 * WISTRIDE)          // 16448
// x halo (fp16): [8 chg][23 rows][24 cols][4 ch] ; 4 fp16 ch = 8 B = 2 u32.
// row stride 24*2 = 48 u32 (== 16 mod 32); chunk 23*48 = 1104 -> pad 1106
// (== 18 mod 32). Warp = 8 chg x 4 rows: banks (18c + 16r) cover every even
// bank exactly twice; 8B spans even+odd -> every bank 2 requests -> the
// 256 B warp access resolves in the minimum 2 wavefronts.
#define XROWU 48                            // u32 per padded halo row
#define XCHUNK2 1106                        // u32 per chg
#define XS_U32 (8 * XCHUNK2)                // 8848
#define SMEM_FLOATS (W3_FLOATS + XS_U32 + 529 + 256)
#define SMEM_BYTES (SMEM_FLOATS * 4)        // 104,324 B -> 2 CTAs/SM

typedef unsigned long long ull;

__device__ __forceinline__ ull pack2(float a, float b) {
    ull r; asm("mov.b64 %0, {%1, %2};" : "=l"(r) : "f"(a), "f"(b)); return r;
}
__device__ __forceinline__ void fma2(ull& d, ull a, ull b) {
    asm("fma.rn.f32x2 %0, %1, %2, %0;" : "+l"(d) : "l"(a), "l"(b));
}
__device__ __forceinline__ float2 unpack2(ull v) {
    float2 f; asm("mov.b64 {%0, %1}, %2;" : "=f"(f.x), "=f"(f.y) : "l"(v)); return f;
}
__device__ __forceinline__ void cp_async16(float* smem_dst, const float* gsrc) {
    uint32_t s = (uint32_t)__cvta_generic_to_shared(smem_dst);
    asm volatile("cp.async.cg.shared.global [%0], [%1], 16;\n"
                 :: "r"(s), "l"(gsrc));
}
__device__ __forceinline__ void cp_async4(float* smem_dst, const float* gsrc, bool pred) {
    uint32_t s = (uint32_t)__cvta_generic_to_shared(smem_dst);
    int sz = pred ? 4 : 0;
    asm volatile("cp.async.ca.shared.global [%0], [%1], 4, %2;\n"
                 :: "r"(s), "l"(gsrc), "r"(sz));
}
__device__ __forceinline__ void cp_commit() {
    asm volatile("cp.async.commit_group;\n" ::: "memory");
}
template <int N> __device__ __forceinline__ void cp_wait() {
    asm volatile("cp.async.wait_group %0;\n" :: "n"(N) : "memory");
}

// ---- stage one 32-channel x pass: LDG fp32 -> cvt fp16 -> STS (8 B) ----
// Consecutive lanes: 8 chg x 4 pixels -> gmem reads are 4 x 128 B coalesced.
__device__ __forceinline__ void stage_x(uint32_t* xs2, const float* __restrict__ gx,
                                        int bi, int bj, int pass, int tid) {
    const int cbase = pass * 32;
    #pragma unroll 4
    for (int u = tid; u < 529 * 8; u += 256) {
        int q = u & 7, pix = u >> 3;
        int hr = pix / 23, hc = pix - hr * 23;
        int gr = bi + hr - 3, gcl = bj + hc - 3;
        float4 v = make_float4(0.f, 0.f, 0.f, 0.f);
        if ((unsigned)gr < H && (unsigned)gcl < W)
            v = *(const float4*)(gx + (((size_t)gr * W + gcl) * C + cbase + q * 4));
        __half2 h0 = __float22half2_rn(make_float2(v.x, v.y));
        __half2 h1 = __float22half2_rn(make_float2(v.z, v.w));
        uint2 st;
        st.x = *(uint32_t*)&h0;
        st.y = *(uint32_t*)&h1;
        *(uint2*)(xs2 + q * XCHUNK2 + (hr * 24 + hc) * 2) = st;
    }
}

// ---- compute one pass: 1 row x 8 cols x 4 ch per thread (R3 shape, fp16 x) ----
__device__ __forceinline__ void compute_pass(const uint32_t* __restrict__ xs2,
                                             const float* __restrict__ w3,
                                             const float* __restrict__ inv,
                                             float* __restrict__ gout,
                                             int bi, int bj, int cbase,
                                             int row, int j0, int chg) {
    ull acc[8][2];
    #pragma unroll
    for (int j = 0; j < 8; ++j) { acc[j][0] = 0ull; acc[j][1] = 0ull; }

    const uint32_t* xb   = xs2 + chg * XCHUNK2 + j0 * 2;
    const float*    wrow = w3 + row * WISTRIDE + j0 * 64;

    #pragma unroll
    for (int p = 0; p < 8; ++p) {
        // load + convert the 15-position halo row (4 fp16 ch per position)
        ull xf[15][2];
        const uint2* xp = (const uint2*)(xb + (row + p) * XROWU);
        #pragma unroll
        for (int t = 0; t < 15; ++t) {
            uint2 h = xp[t];
            float2 f01 = __half22float2(*(__half2*)&h.x);
            float2 f23 = __half22float2(*(__half2*)&h.y);
            xf[t][0] = pack2(f01.x, f01.y);
            xf[t][1] = pack2(f23.x, f23.y);
        }
        #pragma unroll
        for (int j = 0; j < 8; ++j) {
            #pragma unroll
            for (int qg = 0; qg < 2; ++qg) {
                float4 w4 = *(const float4*)(wrow + j * 64 + p * 8 + qg * 4);
                const int t0 = j + qg * 4;
                ull w0 = pack2(w4.x, w4.x);
                ull w1 = pack2(w4.y, w4.y);
                ull w2 = pack2(w4.z, w4.z);
                ull w3p = pack2(w4.w, w4.w);
                fma2(acc[j][0], xf[t0 + 0][0], w0);
                fma2(acc[j][1], xf[t0 + 0][1], w0);
                fma2(acc[j][0], xf[t0 + 1][0], w1);
                fma2(acc[j][1], xf[t0 + 1][1], w1);
                fma2(acc[j][0], xf[t0 + 2][0], w2);
                fma2(acc[j][1], xf[t0 + 2][1], w2);
                fma2(acc[j][0], xf[t0 + 3][0], w3p);
                fma2(acc[j][1], xf[t0 + 3][1], w3p);
            }
        }
    }

    // ---- normalize + store (8 chg lanes -> 128 B contiguous per (row,j)) ----
    #pragma unroll
    for (int j = 0; j < 8; ++j) {
        float s = inv[row * 16 + j0 + j];
        float2 a0 = unpack2(acc[j][0]);
        float2 a1 = unpack2(acc[j][1]);
        float4 v = make_float4(a0.x * s, a0.y * s, a1.x * s, a1.y * s);
        *(float4*)(gout + (((size_t)(bi + row) * W + (bj + j0 + j)) * C
                           + cbase + chg * 4)) = v;
    }
}

__global__ __launch_bounds__(256, 2) void cell_att_kernel(
    const float* __restrict__ gx,   // [H][W][C]
    const float* __restrict__ gw,   // [H][W][64]
    const float* __restrict__ gc,   // [H][W]
    float* __restrict__ gout)       // [H][W][C]
{
    extern __shared__ float smem[];
    float*    w3  = smem;                        // fp32 weights
    uint32_t* xs2 = (uint32_t*)(w3 + W3_FLOATS); // fp16 x halo
    float*    ch  = (float*)(xs2 + XS_U32);      // 23x23 cnts halo (fp32)
    float*    inv = ch + 529;                    // 256 per-pixel normalizers

    const int tid = threadIdx.x;
    const int chg = tid & 7;            // channel quad (4 ch)
    const int row = (tid >> 3) & 15;    // 0..15
    const int jg  = tid >> 7;           // 0 or 1
    const int j0  = jg * 8;
    const int bi = blockIdx.y * TI, bj = blockIdx.x * TJ;

    // ---- stage weights (cp.async, natural layout) + cnts halo ----
    #pragma unroll 8
    for (int u = tid; u < 256 * 16; u += 256) {
        int quad = u & 15, px = u >> 4;
        int il = px >> 4, jl = px & 15;
        const float* src = gw + ((size_t)(bi + il) * W + (bj + jl)) * 64 + quad * 4;
        cp_async16(w3 + il * WISTRIDE + jl * 64 + quad * 4, src);
    }
    for (int u = tid; u < 529; u += 256) {
        int hr = u / 23, hc = u - hr * 23;
        int gr = bi + hr - 3, gcl = bj + hc - 3;
        bool ok = ((unsigned)gr < H) && ((unsigned)gcl < W);
        const float* src = ok ? gc + (size_t)gr * W + gcl : gc;
        cp_async4(ch + u, src, ok);
    }
    cp_commit();

    // ---- stage x pass 0 (LDGs overlap the in-flight cp.async group) ----
    stage_x(xs2, gx, bi, bj, 0, tid);

    cp_wait<0>();
    __syncthreads();                    // w3, ch, xs2(pass0) all visible

    // ---- normalizer: inv = 1/(att(cnts)+1e-6), one pixel per thread ----
    {
        int il = tid >> 4, jl = tid & 15;
        const float* wpx = w3 + il * WISTRIDE + jl * 64;
        float s = 0.f;
        #pragma unroll
        for (int p = 0; p < 8; ++p)
            #pragma unroll
            for (int q = 0; q < 8; ++q)
                s += ch[(il + p) * 23 + (jl + q)] * wpx[p * 8 + q];
        inv[tid] = 1.0f / (s + 1e-6f);
    }
    __syncthreads();                    // inv visible

    compute_pass(xs2, w3, inv, gout, bi, bj, 0, row, j0, chg);

    #pragma unroll 1
    for (int pass = 1; pass < 4; ++pass) {
        __syncthreads();                // everyone done reading xs2
        stage_x(xs2, gx, bi, bj, pass, tid);
        __syncthreads();                // new xs2 visible
        compute_pass(xs2, w3, inv, gout, bi, bj, pass * 32, row, j0, chg);
    }
}

extern "C" void kernel_launch(void* const* d_in, const int* in_sizes, int n_in,
                              void* d_out, int out_size) {
    const float* x0 = (const float*)d_in[0];
    const float* w  = (const float*)d_in[1];
    const float* c  = (const float*)d_in[2];
    float* out      = (float*)d_out;
    cudaFuncSetAttribute(cell_att_kernel,
                         cudaFuncAttributeMaxDynamicSharedMemorySize, SMEM_BYTES);
    dim3 grid(W / TJ, H / TI);
    cell_att_kernel<<<grid, 256, SMEM_BYTES>>>(x0, w, c, out);
}